// round 8
// baseline (speedup 1.0000x reference)
#include <cuda_runtime.h>

#define N 256
#define TB 256           // threads per block
#define GRID 256         // 1 anchor per block
#define PROW 257         // padded partials row stride (floats)

// Scratch (allocations forbidden)
__device__ float2   g_part[GRID];
__device__ unsigned g_count = 0;

__global__ void __launch_bounds__(TB, 2)
fused_kernel(const int* __restrict__ raw,
             const float* __restrict__ emb,
             float* __restrict__ out) {
    __shared__ float s_p[32 * PROW];        // partials[lane][row]
    __shared__ float s_dn[N];               // masked distances
    __shared__ int   s_lab[N];
    __shared__ float s_wmax[8];
    __shared__ int   s_cnt[8];
    __shared__ float s_ed[N];               // compacted positive distances
    __shared__ float s_val[N];

    const int t    = threadIdx.x;
    const int lane = t & 31;
    const int w    = t >> 5;                // 8 warps
    const int i    = blockIdx.x;            // anchor index

    // --- Label decode (int64 vs int32 autodetect via block vote) ---
    int odd_nonzero = (t < 128) ? (raw[2 * t + 1] != 0) : 0;
    int is_int32 = __syncthreads_or(odd_nonzero);
    s_lab[t] = is_int32 ? raw[t] : raw[2 * t];

    // --- Anchor row: lane = column chunk (coalesced LDG.128, warp-broadcast) ---
    const float4* e4 = reinterpret_cast<const float4*>(emb);
    const float4 a = __ldg(e4 + i * 32 + lane);

    // --- Per-lane partial squared distances; warp w, iter j -> row w+8j ---
    // d^2 = sum (a_i - a_k)^2 over this lane's 4 columns
#pragma unroll 8
    for (int j = 0; j < 32; j++) {
        const int row = w + 8 * j;
        float4 x = __ldg(e4 + row * 32 + lane);      // coalesced 512B per warp
        float dx = x.x - a.x, dy = x.y - a.y, dz = x.z - a.z, dw = x.w - a.w;
        float s = dx * dx + dy * dy + dz * dz + dw * dw;
        s_p[lane * PROW + row] = s;                  // conflict-free STS.32
    }
    __syncthreads();                                 // bar A: partials + labels

    // --- Thread k: transpose-reduce 32 partials (conflict-free LDS.32) ---
    const int k = t;
    float ax = 0.f, bx = 0.f, cx = 0.f, dx4 = 0.f;
#pragma unroll
    for (int l = 0; l < 32; l += 4) {
        ax  += s_p[(l + 0) * PROW + k];
        bx  += s_p[(l + 1) * PROW + k];
        cx  += s_p[(l + 2) * PROW + k];
        dx4 += s_p[(l + 3) * PROW + k];
    }
    const float s2 = (ax + bx) + (cx + dx4);         // fixed combine order
    // clip(.,0) then clip(.,EPS) == max(.,EPS)
    const float d = sqrtf(fmaxf(s2, 1e-4f));

    const int  lk  = s_lab[k], li = s_lab[i];
    const bool neg = (lk != li) || (k == i);         // j-set membership
    const bool pos = (lk == li) && (k != i);

    // masked distance (d >= 0.01 > -1, -1 never passes "> d")
    const float dn = neg ? d : -1.f;
    s_dn[k] = dn;

    float mx = dn;
#pragma unroll
    for (int off = 16; off > 0; off >>= 1)           // fixed-order butterfly
        mx = fmaxf(mx, __shfl_xor_sync(0xffffffffu, mx, off));
    const unsigned bp = __ballot_sync(0xffffffffu, pos);
    if (lane == 0) {
        s_wmax[w] = mx;
        s_cnt[w]  = __popc(bp);
    }
    __syncthreads();                                 // bar B

    // --- Deterministic compaction slots + block maxd + count ---
    int C = 0, pfx = 0;
    float maxd = -1.f;
#pragma unroll
    for (int q = 0; q < 8; q++) {
        int c = s_cnt[q];
        if (q < w) pfx += c;
        C += c;
        maxd = fmaxf(maxd, s_wmax[q]);
    }
    if (pos) {
        unsigned lt = (1u << lane) - 1u;
        s_ed[pfx + __popc(bp & lt)] = d;
    }
    __syncthreads();                                 // bar C

    // --- Warp-cooperative successor-min scan, one entry per warp round ---
    const float4* p4 = reinterpret_cast<const float4*>(s_dn);
    for (int e = w; e < C; e += 8) {
        const float dv = s_ed[e];                    // broadcast
        float4 u = p4[lane], v = p4[lane + 32];      // conflict-free LDS.128
        float m = 3.402823466e+38f;
        if (u.x > dv) m = fminf(m, u.x);
        if (u.y > dv) m = fminf(m, u.y);
        if (u.z > dv) m = fminf(m, u.z);
        if (u.w > dv) m = fminf(m, u.w);
        if (v.x > dv) m = fminf(m, v.x);
        if (v.y > dv) m = fminf(m, v.y);
        if (v.z > dv) m = fminf(m, v.z);
        if (v.w > dv) m = fminf(m, v.w);
#pragma unroll
        for (int off = 16; off > 0; off >>= 1)
            m = fminf(m, __shfl_xor_sync(0xffffffffu, m, off));
        if (lane == 0) {
            // mask_final <=> exists d_ij > d_ik <=> maxd > d_ik
            const float semi = (maxd > dv) ? (dv - m) : (dv - maxd);
            s_val[e] = fmaxf(0.f, semi + 1.0f);
        }
    }
    __syncthreads();                                 // bar D

    // --- Warp 0: fixed-order block sum + cross-block handoff ---
    if (t < 32) {
        float sv = 0.f;
        for (int e = lane; e < C; e += 32) sv += s_val[e];
#pragma unroll
        for (int off = 16; off > 0; off >>= 1)
            sv += __shfl_xor_sync(0xffffffffu, sv, off);

        unsigned rank = 0;
        if (lane == 0) {
            g_part[i] = make_float2(sv, (float)C);
            __threadfence();
            rank = atomicAdd(&g_count, 1u);
        }
        rank = __shfl_sync(0xffffffffu, rank, 0);

        // --- Last block: deterministic final reduction over 256 partials ---
        if (rank == GRID - 1) {
            float sx = 0.f, sy = 0.f;
#pragma unroll
            for (int q = 0; q < 8; q++) {
                const float2* gp = (const float2*)g_part + lane + q * 32;
                float2 vv;
                asm volatile("ld.global.cg.v2.f32 {%0,%1}, [%2];"
                             : "=f"(vv.x), "=f"(vv.y) : "l"(gp));
                sx += vv.x; sy += vv.y;
            }
#pragma unroll
            for (int off = 16; off > 0; off >>= 1) {
                sx += __shfl_xor_sync(0xffffffffu, sx, off);
                sy += __shfl_xor_sync(0xffffffffu, sy, off);
            }
            if (lane == 0) {
                out[0] = sx / sy;
                g_count = 0;                         // reset for replay
            }
        }
    }
}

extern "C" void kernel_launch(void* const* d_in, const int* in_sizes, int n_in,
                              void* d_out, int out_size) {
    const float* emb = (const float*)d_in[0];
    const int*   lab = (const int*)d_in[1];  // int32 view; kernel autodetects int64
    (void)in_sizes; (void)n_in; (void)out_size;

    fused_kernel<<<GRID, TB>>>(lab, emb, (float*)d_out);
}

// round 9
// speedup vs baseline: 1.0029x; 1.0029x over previous
#include <cuda_runtime.h>

#define N 256
#define T 512
#define GRID 128         // 2 anchors per block
#define MAXE 512
#define PROW 257         // padded partials row stride (float2 units)

// Scratch (allocations forbidden)
__device__ float2   g_part[GRID];
__device__ unsigned g_count = 0;

__global__ void __launch_bounds__(T)
fused_kernel(const int* __restrict__ raw,
             const float* __restrict__ emb,
             float* __restrict__ out) {
    __shared__ float2 s_p[8 * PROW];           // partials[colgroup][row], 16.4KB
    __shared__ float  s_dn0[N], s_dn1[N];      // masked distances
    __shared__ int    s_lab[N];
    __shared__ float2 s_wmax[8];
    __shared__ int    s_c0[8], s_c1[8];
    __shared__ float  s_ed[MAXE];              // compacted (sign = anchor)
    __shared__ float  s_val[MAXE];

    const int t    = threadIdx.x;
    const int lane = t & 31;
    const int w    = t >> 5;                   // 16 warps
    const int b    = blockIdx.x;
    const int i0   = 2 * b, i1 = 2 * b + 1;

    // --- Label decode (int64 vs int32 autodetect via block vote) ---
    int odd_nonzero = (t < 128) ? (raw[2 * t + 1] != 0) : 0;
    int is_int32 = __syncthreads_or(odd_nonzero);
    if (t < N) s_lab[t] = is_int32 ? raw[t] : raw[2 * t];

    // --- Anchor rows: lane = column chunk (coalesced LDG.128, broadcast) ---
    const float4* e4 = reinterpret_cast<const float4*>(emb);
    const float4 a0 = __ldg(e4 + i0 * 32 + lane);
    const float4 a1 = __ldg(e4 + i1 * 32 + lane);

    // --- Dot phase: warp w owns rows w+16j. Batched loads (MLP=8), then
    //     per-lane partials over 4 cols, 2-step shuffle combine -> 16-col groups.
#pragma unroll
    for (int g = 0; g < 2; g++) {
        float4 xv[8];
#pragma unroll
        for (int m = 0; m < 8; m++)
            xv[m] = __ldg(e4 + (w + 16 * (8 * g + m)) * 32 + lane);  // coalesced
#pragma unroll
        for (int m = 0; m < 8; m++) {
            const int row = w + 16 * (8 * g + m);
            float4 x = xv[m];
            float dx = x.x - a0.x, dy = x.y - a0.y, dz = x.z - a0.z, dw = x.w - a0.w;
            float s0 = dx * dx + dy * dy + dz * dz + dw * dw;
            dx = x.x - a1.x; dy = x.y - a1.y; dz = x.z - a1.z; dw = x.w - a1.w;
            float s1 = dx * dx + dy * dy + dz * dz + dw * dw;
            // combine 4 lanes (fixed order; only lane%4==0 stores -> deterministic)
            s0 += __shfl_xor_sync(0xffffffffu, s0, 1);
            s1 += __shfl_xor_sync(0xffffffffu, s1, 1);
            s0 += __shfl_xor_sync(0xffffffffu, s0, 2);
            s1 += __shfl_xor_sync(0xffffffffu, s1, 2);
            if ((lane & 3) == 0)
                s_p[(lane >> 2) * PROW + row] = make_float2(s0, s1);
        }
    }
    __syncthreads();                                     // bar A

    // --- Threads 0..255: reduce 8 column-group partials for row k ---
    float d0 = 0.f, d1 = 0.f;
    bool pos0 = false, pos1 = false;
    unsigned b0 = 0, b1 = 0;
    if (t < N) {
        const int k = t;
        float2 p0v = s_p[0 * PROW + k], p1v = s_p[1 * PROW + k];
        float2 p2v = s_p[2 * PROW + k], p3v = s_p[3 * PROW + k];
        float2 p4v = s_p[4 * PROW + k], p5v = s_p[5 * PROW + k];
        float2 p6v = s_p[6 * PROW + k], p7v = s_p[7 * PROW + k];
        const float s0 = ((p0v.x + p1v.x) + (p2v.x + p3v.x))
                       + ((p4v.x + p5v.x) + (p6v.x + p7v.x));   // fixed order
        const float s1 = ((p0v.y + p1v.y) + (p2v.y + p3v.y))
                       + ((p4v.y + p5v.y) + (p6v.y + p7v.y));
        // clip(.,0) then clip(.,EPS) == max(.,EPS)
        d0 = sqrtf(fmaxf(s0, 1e-4f));
        d1 = sqrtf(fmaxf(s1, 1e-4f));

        const int lk = s_lab[k], l0 = s_lab[i0], l1 = s_lab[i1];
        const bool neg0 = (lk != l0) || (k == i0);
        const bool neg1 = (lk != l1) || (k == i1);
        pos0 = (lk == l0) && (k != i0);
        pos1 = (lk == l1) && (k != i1);

        // masked distances (d >= 0.01 > -1, -1 never passes "> d")
        const float dn0 = neg0 ? d0 : -1.f;
        const float dn1 = neg1 ? d1 : -1.f;
        s_dn0[k] = dn0;
        s_dn1[k] = dn1;

        float a = dn0, c = dn1;
#pragma unroll
        for (int off = 16; off > 0; off >>= 1) {         // fixed-order butterfly
            a = fmaxf(a, __shfl_xor_sync(0xffffffffu, a, off));
            c = fmaxf(c, __shfl_xor_sync(0xffffffffu, c, off));
        }
        b0 = __ballot_sync(0xffffffffu, pos0);
        b1 = __ballot_sync(0xffffffffu, pos1);
        if (lane == 0) {
            s_wmax[w] = make_float2(a, c);
            s_c0[w] = __popc(b0);
            s_c1[w] = __popc(b1);
        }
    }
    __syncthreads();                                     // bar B

    // --- Deterministic compaction slots + block maxd + counts ---
    int C0 = 0, C1 = 0, p0 = 0, p1 = 0;
    float max0 = -1.f, max1 = -1.f;
#pragma unroll
    for (int q = 0; q < 8; q++) {
        int c0 = s_c0[q], c1 = s_c1[q];
        if (q < w) { p0 += c0; p1 += c1; }
        C0 += c0; C1 += c1;
        float2 wm = s_wmax[q];
        max0 = fmaxf(max0, wm.x);
        max1 = fmaxf(max1, wm.y);
    }
    const int C = C0 + C1;

    if (t < N) {
        unsigned lt = (1u << lane) - 1u;
        // anchor0 entries in [0, C0): +d0; anchor1 in [C0, C): -d1
        if (pos0) s_ed[p0 + __popc(b0 & lt)] = d0;
        if (pos1) s_ed[C0 + p1 + __popc(b1 & lt)] = -d1;
    }
    __syncthreads();                                     // bar C

    // --- Warp-cooperative successor-min scan, one entry per warp round ---
    for (int e = w; e < C; e += 16) {
        float dve = s_ed[e];                             // broadcast
        const bool  a1f = (dve < 0.f);
        const float dv  = fabsf(dve);
        const float4* p = a1f ? (const float4*)s_dn1 : (const float4*)s_dn0;
        float4 u = p[lane], v = p[lane + 32];            // conflict-free LDS.128
        float m = 3.402823466e+38f;
        if (u.x > dv) m = fminf(m, u.x);
        if (u.y > dv) m = fminf(m, u.y);
        if (u.z > dv) m = fminf(m, u.z);
        if (u.w > dv) m = fminf(m, u.w);
        if (v.x > dv) m = fminf(m, v.x);
        if (v.y > dv) m = fminf(m, v.y);
        if (v.z > dv) m = fminf(m, v.z);
        if (v.w > dv) m = fminf(m, v.w);
#pragma unroll
        for (int off = 16; off > 0; off >>= 1)
            m = fminf(m, __shfl_xor_sync(0xffffffffu, m, off));
        if (lane == 0) {
            const float mx = a1f ? max1 : max0;
            // mask_final <=> exists d_ij > d_ik <=> maxd > d_ik
            const float semi = (mx > dv) ? (dv - m) : (dv - mx);
            s_val[e] = fmaxf(0.f, semi + 1.0f);
        }
    }
    __syncthreads();                                     // bar D

    // --- Warp 0: fixed-order block sum + cross-block handoff ---
    if (t < 32) {
        float sv = 0.f;
        for (int e = lane; e < C; e += 32) sv += s_val[e];
#pragma unroll
        for (int off = 16; off > 0; off >>= 1)
            sv += __shfl_xor_sync(0xffffffffu, sv, off);

        unsigned rank = 0;
        if (lane == 0) {
            g_part[b] = make_float2(sv, (float)C);
            __threadfence();
            rank = atomicAdd(&g_count, 1u);
        }
        rank = __shfl_sync(0xffffffffu, rank, 0);

        // --- Last block: deterministic final reduction over 128 partials ---
        if (rank == GRID - 1) {
            float sx = 0.f, sy = 0.f;
#pragma unroll
            for (int q = 0; q < 4; q++) {
                const float2* gp = (const float2*)g_part + lane + q * 32;
                float2 vv;
                asm volatile("ld.global.cg.v2.f32 {%0,%1}, [%2];"
                             : "=f"(vv.x), "=f"(vv.y) : "l"(gp));
                sx += vv.x; sy += vv.y;
            }
#pragma unroll
            for (int off = 16; off > 0; off >>= 1) {
                sx += __shfl_xor_sync(0xffffffffu, sx, off);
                sy += __shfl_xor_sync(0xffffffffu, sy, off);
            }
            if (lane == 0) {
                out[0] = sx / sy;
                g_count = 0;                             // reset for replay
            }
        }
    }
}

extern "C" void kernel_launch(void* const* d_in, const int* in_sizes, int n_in,
                              void* d_out, int out_size) {
    const float* emb = (const float*)d_in[0];
    const int*   lab = (const int*)d_in[1];  // int32 view; kernel autodetects int64
    (void)in_sizes; (void)n_in; (void)out_size;

    fused_kernel<<<GRID, T>>>(lab, emb, (float*)d_out);
}

// round 11
// speedup vs baseline: 1.0650x; 1.0619x over previous
#include <cuda_runtime.h>

#define N 256
#define T 512
#define GRID 256         // 1 anchor per block, 2 blocks co-resident per SM
#define PROW 257         // padded partials row stride (floats)

// Scratch (allocations forbidden)
__device__ float2   g_part[GRID];
__device__ unsigned g_count = 0;

__global__ void __launch_bounds__(T, 2)
fused_kernel(const int* __restrict__ raw,
             const float* __restrict__ emb,
             float* __restrict__ out) {
    __shared__ float s_p[32 * PROW];           // partials[lane][row], 32.9KB
    __shared__ float s_dn[N];                  // masked distances
    __shared__ int   s_lab[N];
    __shared__ float s_wmax[8];
    __shared__ int   s_cnt[8];
    __shared__ float s_ed[N];                  // compacted positive distances
    __shared__ float s_val[N];

    const int t    = threadIdx.x;
    const int lane = t & 31;
    const int w    = t >> 5;                   // 16 warps
    const int i    = blockIdx.x;               // anchor index

    // --- Anchor row first: coalesced LDG.128, same addr across warps ---
    const float4* e4 = reinterpret_cast<const float4*>(emb);
    const float4 a = __ldg(e4 + i * 32 + lane);

    // --- Warp-local label decode (warps 0-7; no block barrier needed).
    //     Detection probes odd words within the FIRST 256 int32 words only
    //     (in-bounds for both int32[256] and int64[256] layouts):
    //       int64 -> raw[2*(t&127)+1] is a zero high-word  -> is64
    //       int32 -> it's a random label 0..15; P(32 zeros) = 16^-32 ~ 0
    if (w < 8) {
        const int k = t;                       // 0..255
        int probe = raw[2 * (t & 127) + 1];
        int is64 = !__any_sync(0xffffffffu, probe != 0);
        s_lab[k] = is64 ? raw[2 * k] : raw[k];
    }

    // --- Dot phase: warp w owns rows w+16j ---
    // d^2 = sum (a_i - a_k)^2 ; per-lane partial over 4 columns
#pragma unroll
    for (int j = 0; j < 16; j++) {
        const int row = w + 16 * j;
        float4 x = __ldg(e4 + row * 32 + lane);      // coalesced 512B per warp
        float dx = x.x - a.x, dy = x.y - a.y, dz = x.z - a.z, dw = x.w - a.w;
        s_p[lane * PROW + row] = dx * dx + dy * dy + dz * dz + dw * dw;
    }
    __syncthreads();                                 // bar A: partials + labels

    // --- Threads 0..255: transpose-reduce 32 partials for row k ---
    float d = 0.f;
    bool pos = false;
    unsigned bp = 0;
    if (t < N) {
        const int k = t;
        float ax = 0.f, bx = 0.f, cx = 0.f, dx4 = 0.f;
#pragma unroll
        for (int l = 0; l < 32; l += 4) {            // conflict-free LDS.32
            ax  += s_p[(l + 0) * PROW + k];
            bx  += s_p[(l + 1) * PROW + k];
            cx  += s_p[(l + 2) * PROW + k];
            dx4 += s_p[(l + 3) * PROW + k];
        }
        const float s2 = (ax + bx) + (cx + dx4);     // fixed combine order
        // clip(.,0) then clip(.,EPS) == max(.,EPS)
        d = sqrtf(fmaxf(s2, 1e-4f));

        const int  lk  = s_lab[k], li = s_lab[i];
        const bool neg = (lk != li) || (k == i);     // j-set membership
        pos = (lk == li) && (k != i);

        // masked distance (d >= 0.01 > -1, -1 never passes "> d")
        const float dn = neg ? d : -1.f;
        s_dn[k] = dn;

        float mx = dn;
#pragma unroll
        for (int off = 16; off > 0; off >>= 1)       // fixed-order butterfly
            mx = fmaxf(mx, __shfl_xor_sync(0xffffffffu, mx, off));
        bp = __ballot_sync(0xffffffffu, pos);
        if (lane == 0) {
            s_wmax[w] = mx;
            s_cnt[w]  = __popc(bp);
        }
    }
    __syncthreads();                                 // bar B

    // --- Deterministic compaction slots + block maxd + count (all threads) ---
    int C = 0, pfx = 0;
    float maxd = -1.f;
#pragma unroll
    for (int q = 0; q < 8; q++) {
        int c = s_cnt[q];
        if (q < w) pfx += c;
        C += c;
        maxd = fmaxf(maxd, s_wmax[q]);
    }
    if (pos) {
        unsigned lt = (1u << lane) - 1u;
        s_ed[pfx + __popc(bp & lt)] = d;
    }
    __syncthreads();                                 // bar C

    // --- Warp-cooperative successor-min scan; C ~ 15 => one round ---
    const float4* p4 = reinterpret_cast<const float4*>(s_dn);
    for (int e = w; e < C; e += 16) {
        const float dv = s_ed[e];                    // broadcast
        float4 u = p4[lane], v = p4[lane + 32];      // conflict-free LDS.128
        float m = 3.402823466e+38f;
        if (u.x > dv) m = fminf(m, u.x);
        if (u.y > dv) m = fminf(m, u.y);
        if (u.z > dv) m = fminf(m, u.z);
        if (u.w > dv) m = fminf(m, u.w);
        if (v.x > dv) m = fminf(m, v.x);
        if (v.y > dv) m = fminf(m, v.y);
        if (v.z > dv) m = fminf(m, v.z);
        if (v.w > dv) m = fminf(m, v.w);
#pragma unroll
        for (int off = 16; off > 0; off >>= 1)
            m = fminf(m, __shfl_xor_sync(0xffffffffu, m, off));
        if (lane == 0) {
            // mask_final <=> exists d_ij > d_ik <=> maxd > d_ik
            const float semi = (maxd > dv) ? (dv - m) : (dv - maxd);
            s_val[e] = fmaxf(0.f, semi + 1.0f);
        }
    }
    __syncthreads();                                 // bar D

    // --- Warp 0: fixed-order block sum + cross-block handoff ---
    if (t < 32) {
        float sv = 0.f;
        for (int e = lane; e < C; e += 32) sv += s_val[e];
#pragma unroll
        for (int off = 16; off > 0; off >>= 1)
            sv += __shfl_xor_sync(0xffffffffu, sv, off);

        unsigned rank = 0;
        if (lane == 0) {
            g_part[i] = make_float2(sv, (float)C);
            __threadfence();
            rank = atomicAdd(&g_count, 1u);
        }
        rank = __shfl_sync(0xffffffffu, rank, 0);

        // --- Last block: deterministic final reduction over 256 partials ---
        if (rank == GRID - 1) {
            float sx = 0.f, sy = 0.f;
#pragma unroll
            for (int q = 0; q < 8; q++) {
                const float2* gp = (const float2*)g_part + lane + q * 32;
                float2 vv;
                asm volatile("ld.global.cg.v2.f32 {%0,%1}, [%2];"
                             : "=f"(vv.x), "=f"(vv.y) : "l"(gp));
                sx += vv.x; sy += vv.y;
            }
#pragma unroll
            for (int off = 16; off > 0; off >>= 1) {
                sx += __shfl_xor_sync(0xffffffffu, sx, off);
                sy += __shfl_xor_sync(0xffffffffu, sy, off);
            }
            if (lane == 0) {
                out[0] = sx / sy;
                g_count = 0;                         // reset for replay
            }
        }
    }
}

extern "C" void kernel_launch(void* const* d_in, const int* in_sizes, int n_in,
                              void* d_out, int out_size) {
    const float* emb = (const float*)d_in[0];
    const int*   lab = (const int*)d_in[1];  // int32 view; kernel autodetects int64
    (void)in_sizes; (void)n_in; (void)out_size;

    fused_kernel<<<GRID, T>>>(lab, emb, (float*)d_out);
}